// round 1
// baseline (speedup 1.0000x reference)
#include <cuda_runtime.h>
#include <cuda_bf16.h>

#define G  32
#define NV 64
#define H  256
#define M_ROWS (G * NV)

// Scratch (allocation-free rule: __device__ globals)
__device__ float g_C[M_ROWS * H];
__device__ float g_Y[M_ROWS * H];
__device__ int   g_act[G * NV];
__device__ int   g_nact[G];

// ---------------------------------------------------------------------------
// Stage A: C = z @ Wc^T + bc ; Y = z @ Wy^T + by   (blockIdx.z selects matrix)
// out[m][n] = sum_k z[m][k] * W[n][k] + b[n]
// 64x64 tile, K-step 16, 256 threads, 4x4 microtile per thread.
// ---------------------------------------------------------------------------
__global__ void __launch_bounds__(256) gemm_kernel(
    const float* __restrict__ z,
    const float* __restrict__ Wc, const float* __restrict__ bc,
    const float* __restrict__ Wy, const float* __restrict__ by)
{
    const float* __restrict__ W    = blockIdx.z ? Wy : Wc;
    const float* __restrict__ bias = blockIdx.z ? by : bc;
    float* __restrict__ outp       = blockIdx.z ? g_Y : g_C;

    __shared__ float As[16][68];   // [k][m], pad 68 keeps 16B alignment
    __shared__ float Bs[16][68];   // [k][n]

    const int t  = threadIdx.x;
    const int tm = t >> 4;          // 0..15
    const int tn = t & 15;          // 0..15
    const int m0 = blockIdx.y * 64;
    const int n0 = blockIdx.x * 64;
    const int lr = t >> 2;          // 0..63 row within tile
    const int lc = (t & 3) * 4;     // 0,4,8,12 k-offset

    const float* zp = z + (size_t)(m0 + lr) * H + lc;
    const float* wp = W + (size_t)(n0 + lr) * H + lc;

    float acc[4][4];
#pragma unroll
    for (int i = 0; i < 4; i++)
#pragma unroll
        for (int j = 0; j < 4; j++) acc[i][j] = 0.0f;

    for (int k0 = 0; k0 < H; k0 += 16) {
        float4 av = *reinterpret_cast<const float4*>(zp + k0);
        float4 bv = *reinterpret_cast<const float4*>(wp + k0);
        __syncthreads();
        As[lc + 0][lr] = av.x; As[lc + 1][lr] = av.y;
        As[lc + 2][lr] = av.z; As[lc + 3][lr] = av.w;
        Bs[lc + 0][lr] = bv.x; Bs[lc + 1][lr] = bv.y;
        Bs[lc + 2][lr] = bv.z; Bs[lc + 3][lr] = bv.w;
        __syncthreads();
#pragma unroll
        for (int k = 0; k < 16; k++) {
            float4 a4 = *reinterpret_cast<const float4*>(&As[k][tm * 4]);
            float4 b4 = *reinterpret_cast<const float4*>(&Bs[k][tn * 4]);
            float a[4] = {a4.x, a4.y, a4.z, a4.w};
            float b[4] = {b4.x, b4.y, b4.z, b4.w};
#pragma unroll
            for (int i = 0; i < 4; i++)
#pragma unroll
                for (int j = 0; j < 4; j++)
                    acc[i][j] = fmaf(a[i], b[j], acc[i][j]);
        }
    }

    float4 bsv = *reinterpret_cast<const float4*>(&bias[n0 + tn * 4]);
#pragma unroll
    for (int i = 0; i < 4; i++) {
        float4 o;
        o.x = acc[i][0] + bsv.x;
        o.y = acc[i][1] + bsv.y;
        o.z = acc[i][2] + bsv.z;
        o.w = acc[i][3] + bsv.w;
        *reinterpret_cast<float4*>(&outp[(size_t)(m0 + tm * 4 + i) * H + n0 + tn * 4]) = o;
    }
}

// ---------------------------------------------------------------------------
// Stage B: per-graph active-node compaction. 32 blocks x 64 threads.
// ---------------------------------------------------------------------------
__global__ void activity_kernel(const float* __restrict__ mask)
{
    int g = blockIdx.x;
    int j = threadIdx.x;                 // 0..63
    int warp = j >> 5, lane = j & 31;

    float m = mask[g * NV + j];
    bool act = (m > 0.5f);
    unsigned bal = __ballot_sync(0xffffffffu, act);

    __shared__ int wc[2];
    g_act[g * NV + j] = 0;               // pad entries with a valid index
    if (lane == 0) wc[warp] = __popc(bal);
    __syncthreads();

    int base = warp ? wc[0] : 0;
    int pos  = base + __popc(bal & ((1u << lane) - 1u));
    if (act) g_act[g * NV + pos] = j;
    if (j == 0) g_nact[g] = wc[0] + wc[1];
}

// ---------------------------------------------------------------------------
// Stage C: pairwise sigmoid sum over active pairs.
// Block = (row-chunk of 8 active i rows, graph g). 256 threads = h dim.
// sigmoid(x) = 0.5*tanh(0.5*x)+0.5 ; 0.5 factors folded into loads/epilogue.
// ---------------------------------------------------------------------------
#define RPB 8
#define JCH 32

__global__ void __launch_bounds__(256) attn_kernel(float* __restrict__ out)
{
    const int g = blockIdx.y;
    const int nact = g_nact[g];
    const int r0 = blockIdx.x * RPB;
    if (r0 >= nact) return;

    const int h = threadIdx.x;

    __shared__ float ysh[JCH * H];       // 32 KB
    __shared__ int acts[NV];

    if (h < NV) acts[h] = g_act[g * NV + h];
    __syncthreads();

    float a2[RPB], acc[RPB];
#pragma unroll
    for (int r = 0; r < RPB; r++) {
        int rr = r0 + r;                 // rr < 64 always (r0 <= 56)
        int row = acts[rr];
        a2[r] = 0.5f * g_C[(size_t)(g * NV + row) * H + h];
        acc[r] = 0.0f;
    }

    for (int jb = 0; jb < nact; jb += JCH) {
        int jn = min(JCH, nact - jb);
        __syncthreads();
        for (int jj = 0; jj < jn; jj++)
            ysh[jj * H + h] = 0.5f * g_Y[(size_t)(g * NV + acts[jb + jj]) * H + h];
        __syncthreads();
        for (int jj = 0; jj < jn; jj++) {
            float yv = ysh[jj * H + h];
#pragma unroll
            for (int r = 0; r < RPB; r++) {
                float x = a2[r] + yv;
                float th;
                asm("tanh.approx.f32 %0, %1;" : "=f"(th) : "f"(x));
                acc[r] += th;
            }
        }
    }

    const float inv = 1.0f / (float)nact;
    const float half_n = 0.5f * (float)nact;
    const int rmax = min(RPB, nact - r0);
    for (int r = 0; r < rmax; r++) {
        int row = acts[r0 + r];
        out[(size_t)(g * NV + row) * H + h] = (0.5f * acc[r] + half_n) * inv;
    }
}

// ---------------------------------------------------------------------------
// kernel_launch: identify inputs by element count (metadata order:
// num_graphs, nv, z, mask, Wc, bc, Wy, by — scalars skipped).
// ---------------------------------------------------------------------------
extern "C" void kernel_launch(void* const* d_in, const int* in_sizes, int n_in,
                              void* d_out, int out_size)
{
    const float *z = nullptr, *mask = nullptr;
    const float *Wc = nullptr, *bc = nullptr, *Wy = nullptr, *by = nullptr;

    for (int i = 0; i < n_in; i++) {
        int s = in_sizes[i];
        const float* p = (const float*)d_in[i];
        if (s == M_ROWS * H)       z = p;
        else if (s == M_ROWS)      mask = p;
        else if (s == H * H)       { if (!Wc) Wc = p; else Wy = p; }
        else if (s == H)           { if (!bc) bc = p; else by = p; }
    }

    float* out = (float*)d_out;

    gemm_kernel<<<dim3(H / 64, M_ROWS / 64, 2), 256>>>(z, Wc, bc, Wy, by);
    activity_kernel<<<G, NV>>>(mask);
    cudaMemsetAsync(d_out, 0, (size_t)out_size * sizeof(float), 0);
    attn_kernel<<<dim3(NV / RPB, G), 256>>>(out);
}

// round 2
// speedup vs baseline: 1.2529x; 1.2529x over previous
#include <cuda_runtime.h>
#include <cuda_bf16.h>
#include <cstdint>

#define G  32
#define NV 64
#define H  256
#define M_ROWS (G * NV)

// Scratch (allocation-free rule: __device__ globals)
__device__ float g_C[M_ROWS * H];
__device__ float g_Y[M_ROWS * H];
__device__ int   g_act[G * NV];
__device__ int   g_nact[G];

// ---------------------------------------------------------------------------
// Stage A: TF32 tensor-core GEMM.
//   out[m][n] = sum_h z[m][h] * W[n][h] + b[n]
// W row-major [n][h] is exactly B col-major (k=h contiguous) for mma row.col.
// Block tile 128(M) x 64(N), 8 warps (4x2), warp tile 32x32.
// K pipelined in chunks of 16 with cp.async double buffering.
// blockIdx.z selects (Wc,bc,g_C) vs (Wy,by,g_Y).
// ---------------------------------------------------------------------------
#define KC   16
#define LDA  (KC + 4)          // padded stride (words); conflict-free (20g+t pattern)
#define NCH  (H / KC)          // 16 chunks

__device__ __forceinline__ uint32_t f2tf(float f) {
    uint32_t u;
    asm("cvt.rna.tf32.f32 %0, %1;" : "=r"(u) : "f"(f));
    return u;
}

__device__ __forceinline__ void cpa16(uint32_t dst, const float* src) {
    asm volatile("cp.async.cg.shared.global [%0], [%1], 16;" :: "r"(dst), "l"(src));
}

__device__ __forceinline__ void mma_tf32(float c[4], const uint32_t a[4], const uint32_t b[2]) {
    asm volatile(
        "mma.sync.aligned.m16n8k8.row.col.f32.tf32.tf32.f32 "
        "{%0,%1,%2,%3}, {%4,%5,%6,%7}, {%8,%9}, {%0,%1,%2,%3};"
        : "+f"(c[0]), "+f"(c[1]), "+f"(c[2]), "+f"(c[3])
        : "r"(a[0]), "r"(a[1]), "r"(a[2]), "r"(a[3]), "r"(b[0]), "r"(b[1]));
}

__global__ void __launch_bounds__(256) gemm_tc_kernel(
    const float* __restrict__ z,
    const float* __restrict__ Wc, const float* __restrict__ bc,
    const float* __restrict__ Wy, const float* __restrict__ by)
{
    const float* __restrict__ W    = blockIdx.z ? Wy : Wc;
    const float* __restrict__ bias = blockIdx.z ? by : bc;
    float* __restrict__ outp       = blockIdx.z ? g_Y : g_C;

    __shared__ float As[2][128 * LDA];   // [m][k] padded
    __shared__ float Bs[2][ 64 * LDA];   // [n][k] padded

    const int t    = threadIdx.x;
    const int warp = t >> 5;
    const int lane = t & 31;
    const int g    = lane >> 2;          // groupID 0..7
    const int tg   = lane & 3;           // 0..3
    const int wm   = warp & 3;           // 4 warps along M
    const int wn   = warp >> 2;          // 2 warps along N
    const int m0   = blockIdx.y * 128;
    const int n0   = blockIdx.x * 64;

    // gmem->smem staging coordinates (per thread, per chunk)
    const int arow0 = (t) >> 2;          // for f = t
    const int ac40  = (t) & 3;
    const int arow1 = (t + 256) >> 2;
    const int ac41  = (t + 256) & 3;
    const int brow  = t >> 2;
    const int bc4   = t & 3;

    float acc[2][4][4];
#pragma unroll
    for (int mt = 0; mt < 2; mt++)
#pragma unroll
        for (int nt = 0; nt < 4; nt++)
#pragma unroll
            for (int i = 0; i < 4; i++) acc[mt][nt][i] = 0.0f;

    auto issue = [&](int c) {
        const int buf = c & 1;
        const int kc0 = c * KC;
        uint32_t asb = (uint32_t)__cvta_generic_to_shared(&As[buf][0]);
        uint32_t bsb = (uint32_t)__cvta_generic_to_shared(&Bs[buf][0]);
        cpa16(asb + (uint32_t)(arow0 * LDA + ac40 * 4) * 4,
              z + (size_t)(m0 + arow0) * H + kc0 + ac40 * 4);
        cpa16(asb + (uint32_t)(arow1 * LDA + ac41 * 4) * 4,
              z + (size_t)(m0 + arow1) * H + kc0 + ac41 * 4);
        cpa16(bsb + (uint32_t)(brow * LDA + bc4 * 4) * 4,
              W + (size_t)(n0 + brow) * H + kc0 + bc4 * 4);
        asm volatile("cp.async.commit_group;");
    };

    issue(0);

    for (int c = 0; c < NCH; c++) {
        if (c + 1 < NCH) {
            issue(c + 1);
            asm volatile("cp.async.wait_group 1;");
        } else {
            asm volatile("cp.async.wait_group 0;");
        }
        __syncthreads();

        const int buf = c & 1;
        const float* as = &As[buf][0];
        const float* bs = &Bs[buf][0];

#pragma unroll
        for (int ks = 0; ks < KC / 8; ks++) {
            const int kk = ks * 8;
            uint32_t afr[2][4];
#pragma unroll
            for (int mt = 0; mt < 2; mt++) {
                const float* ap = as + (wm * 32 + mt * 16 + g) * LDA + kk + tg;
                afr[mt][0] = f2tf(ap[0]);
                afr[mt][1] = f2tf(ap[8 * LDA]);
                afr[mt][2] = f2tf(ap[4]);
                afr[mt][3] = f2tf(ap[8 * LDA + 4]);
            }
            uint32_t bfr[4][2];
#pragma unroll
            for (int nt = 0; nt < 4; nt++) {
                const float* bp = bs + (wn * 32 + nt * 8 + g) * LDA + kk + tg;
                bfr[nt][0] = f2tf(bp[0]);
                bfr[nt][1] = f2tf(bp[4]);
            }
#pragma unroll
            for (int mt = 0; mt < 2; mt++)
#pragma unroll
                for (int nt = 0; nt < 4; nt++)
                    mma_tf32(acc[mt][nt], afr[mt], bfr[nt]);
        }
        __syncthreads();
    }

    // Epilogue: add bias, write fp32 results
#pragma unroll
    for (int nt = 0; nt < 4; nt++) {
        const int col = n0 + wn * 32 + nt * 8 + 2 * tg;
        const float b0 = __ldg(&bias[col]);
        const float b1 = __ldg(&bias[col + 1]);
#pragma unroll
        for (int mt = 0; mt < 2; mt++) {
            const int row = m0 + wm * 32 + mt * 16 + g;
            float2 o0 = {acc[mt][nt][0] + b0, acc[mt][nt][1] + b1};
            float2 o1 = {acc[mt][nt][2] + b0, acc[mt][nt][3] + b1};
            *reinterpret_cast<float2*>(&outp[(size_t)row * H + col])       = o0;
            *reinterpret_cast<float2*>(&outp[(size_t)(row + 8) * H + col]) = o1;
        }
    }
}

// ---------------------------------------------------------------------------
// Stage B: per-graph active-node compaction. 32 blocks x 64 threads.
// ---------------------------------------------------------------------------
__global__ void activity_kernel(const float* __restrict__ mask)
{
    int g = blockIdx.x;
    int j = threadIdx.x;                 // 0..63
    int warp = j >> 5, lane = j & 31;

    float m = mask[g * NV + j];
    bool act = (m > 0.5f);
    unsigned bal = __ballot_sync(0xffffffffu, act);

    __shared__ int wc[2];
    g_act[g * NV + j] = 0;               // pad entries with a valid index
    if (lane == 0) wc[warp] = __popc(bal);
    __syncthreads();

    int base = warp ? wc[0] : 0;
    int pos  = base + __popc(bal & ((1u << lane) - 1u));
    if (act) g_act[g * NV + pos] = j;
    if (j == 0) g_nact[g] = wc[0] + wc[1];
}

// ---------------------------------------------------------------------------
// Stage C: pairwise sigmoid sum over active pairs.
// sigmoid(x) = 0.5*tanh(0.5*x)+0.5 ; 0.5 factors folded into loads/epilogue.
// ---------------------------------------------------------------------------
#define RPB 8
#define JCH 32

__global__ void __launch_bounds__(256) attn_kernel(float* __restrict__ out)
{
    const int g = blockIdx.y;
    const int nact = g_nact[g];
    const int r0 = blockIdx.x * RPB;
    if (r0 >= nact) return;

    const int h = threadIdx.x;

    __shared__ float ysh[JCH * H];       // 32 KB
    __shared__ int acts[NV];

    if (h < NV) acts[h] = g_act[g * NV + h];
    __syncthreads();

    float a2[RPB], acc[RPB];
#pragma unroll
    for (int r = 0; r < RPB; r++) {
        int rr = r0 + r;                 // rr < 64 always
        int row = acts[rr];
        a2[r] = 0.5f * g_C[(size_t)(g * NV + row) * H + h];
        acc[r] = 0.0f;
    }

    for (int jb = 0; jb < nact; jb += JCH) {
        int jn = min(JCH, nact - jb);
        __syncthreads();
        for (int jj = 0; jj < jn; jj++)
            ysh[jj * H + h] = 0.5f * g_Y[(size_t)(g * NV + acts[jb + jj]) * H + h];
        __syncthreads();
        for (int jj = 0; jj < jn; jj++) {
            float yv = ysh[jj * H + h];
#pragma unroll
            for (int r = 0; r < RPB; r++) {
                float x = a2[r] + yv;
                float th;
                asm("tanh.approx.f32 %0, %1;" : "=f"(th) : "f"(x));
                acc[r] += th;
            }
        }
    }

    const float inv = 1.0f / (float)nact;
    const float half_n = 0.5f * (float)nact;
    const int rmax = min(RPB, nact - r0);
    for (int r = 0; r < rmax; r++) {
        int row = acts[r0 + r];
        out[(size_t)(g * NV + row) * H + h] = (0.5f * acc[r] + half_n) * inv;
    }
}

// ---------------------------------------------------------------------------
// kernel_launch
// ---------------------------------------------------------------------------
extern "C" void kernel_launch(void* const* d_in, const int* in_sizes, int n_in,
                              void* d_out, int out_size)
{
    const float *z = nullptr, *mask = nullptr;
    const float *Wc = nullptr, *bc = nullptr, *Wy = nullptr, *by = nullptr;

    for (int i = 0; i < n_in; i++) {
        int s = in_sizes[i];
        const float* p = (const float*)d_in[i];
        if (s == M_ROWS * H)       z = p;
        else if (s == M_ROWS)      mask = p;
        else if (s == H * H)       { if (!Wc) Wc = p; else Wy = p; }
        else if (s == H)           { if (!bc) bc = p; else by = p; }
    }

    float* out = (float*)d_out;

    gemm_tc_kernel<<<dim3(H / 64, M_ROWS / 128, 2), 256>>>(z, Wc, bc, Wy, by);
    activity_kernel<<<G, NV>>>(mask);
    cudaMemsetAsync(d_out, 0, (size_t)out_size * sizeof(float), 0);
    attn_kernel<<<dim3(NV / RPB, G), 256>>>(out);
}

// round 3
// speedup vs baseline: 1.5222x; 1.2150x over previous
#include <cuda_runtime.h>
#include <cuda_bf16.h>
#include <cstdint>

#define G  32
#define NV 64
#define H  256
#define M_ROWS (G * NV)

// Scratch (allocation-free rule: __device__ globals)
__device__ float g_C[M_ROWS * H];
__device__ float g_Y[M_ROWS * H];

// ---------------------------------------------------------------------------
// Stage A: TF32 tensor-core GEMM, no explicit CVT (HMMA.tf32 reads top 19 bits).
//   out[m][n] = sum_h z[m][h] * W[n][h] + b[n]
// Block tile 64(M) x 64(N), KC=32 double-buffered cp.async, 8 warps,
// warp tile 16(M) x 32(N). Grid (H/64, M/64, 2) = 256 blocks (~2/SM).
// Smem stride 36 words: fragment-read bank = (4g + tg) mod 32 -> conflict-free.
// ---------------------------------------------------------------------------
#define KC   32
#define LDK  36
#define NCH  (H / KC)   // 8 chunks

__device__ __forceinline__ void cpa16(uint32_t dst, const float* src) {
    asm volatile("cp.async.cg.shared.global [%0], [%1], 16;" :: "r"(dst), "l"(src));
}

__device__ __forceinline__ void mma_tf32(float c[4], const uint32_t a[4], const uint32_t b[2]) {
    asm volatile(
        "mma.sync.aligned.m16n8k8.row.col.f32.tf32.tf32.f32 "
        "{%0,%1,%2,%3}, {%4,%5,%6,%7}, {%8,%9}, {%0,%1,%2,%3};"
        : "+f"(c[0]), "+f"(c[1]), "+f"(c[2]), "+f"(c[3])
        : "r"(a[0]), "r"(a[1]), "r"(a[2]), "r"(a[3]), "r"(b[0]), "r"(b[1]));
}

__global__ void __launch_bounds__(256, 2) gemm_tc_kernel(
    const float* __restrict__ z,
    const float* __restrict__ Wc, const float* __restrict__ bc,
    const float* __restrict__ Wy, const float* __restrict__ by)
{
    const float* __restrict__ W    = blockIdx.z ? Wy : Wc;
    const float* __restrict__ bias = blockIdx.z ? by : bc;
    float* __restrict__ outp       = blockIdx.z ? g_Y : g_C;

    __shared__ float As[2][64 * LDK];   // [m][k], stride 36
    __shared__ float Bs[2][64 * LDK];   // [n][k], stride 36

    const int t    = threadIdx.x;
    const int warp = t >> 5;
    const int lane = t & 31;
    const int g    = lane >> 2;          // 0..7
    const int tg   = lane & 3;           // 0..3
    const int wm   = warp & 3;           // 4 warps along M (16 rows each)
    const int wn   = warp >> 2;          // 2 warps along N (32 cols each)
    const int m0   = blockIdx.y * 64;
    const int n0   = blockIdx.x * 64;

    // staging: 512 slots of 16B per matrix per chunk; 2 slots/thread
    const int r0s = t >> 3,        kg0 = t & 7;           // slot t
    const int r1s = (t + 256) >> 3, kg1 = (t + 256) & 7;  // slot t+256

    float acc[4][4];
#pragma unroll
    for (int nt = 0; nt < 4; nt++)
#pragma unroll
        for (int i = 0; i < 4; i++) acc[nt][i] = 0.0f;

    auto issue = [&](int c) {
        const int buf = c & 1;
        const int kc0 = c * KC;
        uint32_t asb = (uint32_t)__cvta_generic_to_shared(&As[buf][0]);
        uint32_t bsb = (uint32_t)__cvta_generic_to_shared(&Bs[buf][0]);
        cpa16(asb + (uint32_t)(r0s * LDK + kg0 * 4) * 4, z + (size_t)(m0 + r0s) * H + kc0 + kg0 * 4);
        cpa16(asb + (uint32_t)(r1s * LDK + kg1 * 4) * 4, z + (size_t)(m0 + r1s) * H + kc0 + kg1 * 4);
        cpa16(bsb + (uint32_t)(r0s * LDK + kg0 * 4) * 4, W + (size_t)(n0 + r0s) * H + kc0 + kg0 * 4);
        cpa16(bsb + (uint32_t)(r1s * LDK + kg1 * 4) * 4, W + (size_t)(n0 + r1s) * H + kc0 + kg1 * 4);
        asm volatile("cp.async.commit_group;");
    };

    issue(0);

    for (int c = 0; c < NCH; c++) {
        if (c + 1 < NCH) {
            issue(c + 1);
            asm volatile("cp.async.wait_group 1;");
        } else {
            asm volatile("cp.async.wait_group 0;");
        }
        __syncthreads();

        const uint32_t* as = reinterpret_cast<const uint32_t*>(&As[c & 1][0]);
        const uint32_t* bs = reinterpret_cast<const uint32_t*>(&Bs[c & 1][0]);

#pragma unroll
        for (int ks = 0; ks < KC / 8; ks++) {
            const int kk = ks * 8;
            uint32_t afr[4];
            {
                const uint32_t* ap = as + (wm * 16 + g) * LDK + kk + tg;
                afr[0] = ap[0];
                afr[1] = ap[8 * LDK];
                afr[2] = ap[4];
                afr[3] = ap[8 * LDK + 4];
            }
            uint32_t bfr[4][2];
#pragma unroll
            for (int nt = 0; nt < 4; nt++) {
                const uint32_t* bp = bs + (wn * 32 + nt * 8 + g) * LDK + kk + tg;
                bfr[nt][0] = bp[0];
                bfr[nt][1] = bp[4];
            }
#pragma unroll
            for (int nt = 0; nt < 4; nt++)
                mma_tf32(acc[nt], afr, bfr[nt]);
        }
        __syncthreads();
    }

    // Epilogue: bias + fp32 store
#pragma unroll
    for (int nt = 0; nt < 4; nt++) {
        const int col = n0 + wn * 32 + nt * 8 + 2 * tg;
        const float b0 = __ldg(&bias[col]);
        const float b1 = __ldg(&bias[col + 1]);
        const int row = m0 + wm * 16 + g;
        float2 o0 = {acc[nt][0] + b0, acc[nt][1] + b1};
        float2 o1 = {acc[nt][2] + b0, acc[nt][3] + b1};
        *reinterpret_cast<float2*>(&outp[(size_t)row * H + col])       = o0;
        *reinterpret_cast<float2*>(&outp[(size_t)(row + 8) * H + col]) = o1;
    }
}

// ---------------------------------------------------------------------------
// Stage B: pairwise sigmoid sum, with in-block mask compaction and
// zero-fill of inactive rows (replaces activity kernel + memset).
// sigmoid(x) = 0.5*tanh(0.5*x)+0.5 ; 0.5 folded into loads/epilogue.
// Block = (4 rows of the full 64-entry list, graph). 256 threads = h dim.
// List layout: entries [0, nact) = active node ids, [nact, 64) = inactive.
// ---------------------------------------------------------------------------
#define RPB 4
#define JCH 32

__global__ void __launch_bounds__(256) attn_kernel(
    const float* __restrict__ mask, float* __restrict__ out)
{
    const int gg = blockIdx.y;
    const int r0 = blockIdx.x * RPB;
    const int h  = threadIdx.x;

    __shared__ float ysh[JCH * H];       // 32 KB
    __shared__ int acts[NV];
    __shared__ int s_cnt[2];
    __shared__ int s_nact;

    // ---- in-block compaction (threads 0..63, warps 0 and 1) ----
    bool act = false;
    unsigned bal = 0;
    if (h < NV) {
        act = (mask[gg * NV + h] > 0.5f);
        bal = __ballot_sync(0xffffffffu, act);
        if ((h & 31) == 0) s_cnt[h >> 5] = __popc(bal);
    }
    __syncthreads();
    if (h < NV) {
        const int warp = h >> 5, lane = h & 31;
        const int a0 = s_cnt[0], a1 = s_cnt[1];
        const int nact = a0 + a1;
        const int pre  = __popc(bal & ((1u << lane) - 1u));
        const int preI = lane - pre;
        const int pos = act ? ((warp ? a0 : 0) + pre)
                            : (nact + (warp ? (32 - a0) : 0) + preI);
        acts[pos] = h;
        if (h == 0) s_nact = nact;
    }
    __syncthreads();

    const int nact = s_nact;

    float a2[RPB], acc[RPB];
#pragma unroll
    for (int r = 0; r < RPB; r++) {
        const int row = acts[r0 + r];
        a2[r] = 0.5f * g_C[(size_t)(gg * NV + row) * H + h];
        acc[r] = 0.0f;
    }

    if (r0 < nact) {
        for (int jb = 0; jb < nact; jb += JCH) {
            const int jn = min(JCH, nact - jb);
            __syncthreads();
            for (int jj = 0; jj < jn; jj++)
                ysh[jj * H + h] = 0.5f * g_Y[(size_t)(gg * NV + acts[jb + jj]) * H + h];
            __syncthreads();
            for (int jj = 0; jj < jn; jj++) {
                const float yv = ysh[jj * H + h];
#pragma unroll
                for (int r = 0; r < RPB; r++) {
                    float x = a2[r] + yv;
                    float th;
                    asm("tanh.approx.f32 %0, %1;" : "=f"(th) : "f"(x));
                    acc[r] += th;
                }
            }
        }
    }

    const float inv    = nact ? (1.0f / (float)nact) : 0.0f;
    const float half_n = 0.5f * (float)nact;
#pragma unroll
    for (int r = 0; r < RPB; r++) {
        const int rr = r0 + r;
        const int row = acts[rr];
        float v = (rr < nact) ? (0.5f * acc[r] + half_n) * inv : 0.0f;
        out[(size_t)(gg * NV + row) * H + h] = v;
    }
}

// ---------------------------------------------------------------------------
// kernel_launch
// ---------------------------------------------------------------------------
extern "C" void kernel_launch(void* const* d_in, const int* in_sizes, int n_in,
                              void* d_out, int out_size)
{
    const float *z = nullptr, *mask = nullptr;
    const float *Wc = nullptr, *bc = nullptr, *Wy = nullptr, *by = nullptr;

    for (int i = 0; i < n_in; i++) {
        int s = in_sizes[i];
        const float* p = (const float*)d_in[i];
        if (s == M_ROWS * H)       z = p;
        else if (s == M_ROWS)      mask = p;
        else if (s == H * H)       { if (!Wc) Wc = p; else Wy = p; }
        else if (s == H)           { if (!bc) bc = p; else by = p; }
    }

    float* out = (float*)d_out;

    gemm_tc_kernel<<<dim3(H / 64, M_ROWS / 64, 2), 256>>>(z, Wc, bc, Wy, by);
    attn_kernel<<<dim3(NV / RPB, G), 256>>>(mask, out);
}

// round 4
// speedup vs baseline: 1.9594x; 1.2872x over previous
#include <cuda_runtime.h>
#include <cuda_bf16.h>
#include <cstdint>

#define G  32
#define NV 64
#define H  256
#define M_ROWS (G * NV)

// Scratch (allocation-free rule: __device__ globals)
__device__ float g_C[M_ROWS * H];
__device__ float g_Y[M_ROWS * H];

// ---------------------------------------------------------------------------
// Stage A: TF32 tensor-core GEMM, no explicit CVT (HMMA.tf32 reads top 19 bits).
//   out[m][n] = sum_h z[m][h] * W[n][h] + b[n]
// Block tile 64(M) x 64(N), KC=32 double-buffered cp.async, 8 warps,
// warp tile 16(M) x 32(N). Grid (H/64, M/64, 2) = 256 blocks (~2/SM).
// ---------------------------------------------------------------------------
#define KC   32
#define LDK  36
#define NCH  (H / KC)   // 8 chunks

__device__ __forceinline__ void cpa16(uint32_t dst, const float* src) {
    asm volatile("cp.async.cg.shared.global [%0], [%1], 16;" :: "r"(dst), "l"(src));
}

__device__ __forceinline__ void mma_tf32(float c[4], const uint32_t a[4], const uint32_t b[2]) {
    asm volatile(
        "mma.sync.aligned.m16n8k8.row.col.f32.tf32.tf32.f32 "
        "{%0,%1,%2,%3}, {%4,%5,%6,%7}, {%8,%9}, {%0,%1,%2,%3};"
        : "+f"(c[0]), "+f"(c[1]), "+f"(c[2]), "+f"(c[3])
        : "r"(a[0]), "r"(a[1]), "r"(a[2]), "r"(a[3]), "r"(b[0]), "r"(b[1]));
}

__global__ void __launch_bounds__(256, 2) gemm_tc_kernel(
    const float* __restrict__ z,
    const float* __restrict__ Wc, const float* __restrict__ bc,
    const float* __restrict__ Wy, const float* __restrict__ by)
{
    const float* __restrict__ W    = blockIdx.z ? Wy : Wc;
    const float* __restrict__ bias = blockIdx.z ? by : bc;
    float* __restrict__ outp       = blockIdx.z ? g_Y : g_C;

    __shared__ float As[2][64 * LDK];
    __shared__ float Bs[2][64 * LDK];

    const int t    = threadIdx.x;
    const int warp = t >> 5;
    const int lane = t & 31;
    const int g    = lane >> 2;
    const int tg   = lane & 3;
    const int wm   = warp & 3;
    const int wn   = warp >> 2;
    const int m0   = blockIdx.y * 64;
    const int n0   = blockIdx.x * 64;

    const int r0s = t >> 3,         kg0 = t & 7;
    const int r1s = (t + 256) >> 3, kg1 = (t + 256) & 7;

    float acc[4][4];
#pragma unroll
    for (int nt = 0; nt < 4; nt++)
#pragma unroll
        for (int i = 0; i < 4; i++) acc[nt][i] = 0.0f;

    auto issue = [&](int c) {
        const int buf = c & 1;
        const int kc0 = c * KC;
        uint32_t asb = (uint32_t)__cvta_generic_to_shared(&As[buf][0]);
        uint32_t bsb = (uint32_t)__cvta_generic_to_shared(&Bs[buf][0]);
        cpa16(asb + (uint32_t)(r0s * LDK + kg0 * 4) * 4, z + (size_t)(m0 + r0s) * H + kc0 + kg0 * 4);
        cpa16(asb + (uint32_t)(r1s * LDK + kg1 * 4) * 4, z + (size_t)(m0 + r1s) * H + kc0 + kg1 * 4);
        cpa16(bsb + (uint32_t)(r0s * LDK + kg0 * 4) * 4, W + (size_t)(n0 + r0s) * H + kc0 + kg0 * 4);
        cpa16(bsb + (uint32_t)(r1s * LDK + kg1 * 4) * 4, W + (size_t)(n0 + r1s) * H + kc0 + kg1 * 4);
        asm volatile("cp.async.commit_group;");
    };

    issue(0);

    for (int c = 0; c < NCH; c++) {
        if (c + 1 < NCH) {
            issue(c + 1);
            asm volatile("cp.async.wait_group 1;");
        } else {
            asm volatile("cp.async.wait_group 0;");
        }
        __syncthreads();

        const uint32_t* as = reinterpret_cast<const uint32_t*>(&As[c & 1][0]);
        const uint32_t* bs = reinterpret_cast<const uint32_t*>(&Bs[c & 1][0]);

#pragma unroll
        for (int ks = 0; ks < KC / 8; ks++) {
            const int kk = ks * 8;
            uint32_t afr[4];
            {
                const uint32_t* ap = as + (wm * 16 + g) * LDK + kk + tg;
                afr[0] = ap[0];
                afr[1] = ap[8 * LDK];
                afr[2] = ap[4];
                afr[3] = ap[8 * LDK + 4];
            }
            uint32_t bfr[4][2];
#pragma unroll
            for (int nt = 0; nt < 4; nt++) {
                const uint32_t* bp = bs + (wn * 32 + nt * 8 + g) * LDK + kk + tg;
                bfr[nt][0] = bp[0];
                bfr[nt][1] = bp[4];
            }
#pragma unroll
            for (int nt = 0; nt < 4; nt++)
                mma_tf32(acc[nt], afr, bfr[nt]);
        }
        __syncthreads();
    }

#pragma unroll
    for (int nt = 0; nt < 4; nt++) {
        const int col = n0 + wn * 32 + nt * 8 + 2 * tg;
        const float b0 = __ldg(&bias[col]);
        const float b1 = __ldg(&bias[col + 1]);
        const int row = m0 + wm * 16 + g;
        float2 o0 = {acc[nt][0] + b0, acc[nt][1] + b1};
        float2 o1 = {acc[nt][2] + b0, acc[nt][3] + b1};
        *reinterpret_cast<float2*>(&outp[(size_t)row * H + col])       = o0;
        *reinterpret_cast<float2*>(&outp[(size_t)(row + 8) * H + col]) = o1;
    }
}

// ---------------------------------------------------------------------------
// Stage B: pairwise sigmoid sum with in-block compaction + zero-fill.
// sigmoid(x) = 0.5*tanh(0.5*x)+0.5.
// a2[r] = 0.5*c ; x = fma(0.5, y, a2[r]).
// jj loop unrolled x4 with prefetched LDS -> 16 independent MUFU chains.
// y staged raw (unscaled) via cp.async, scale folded into the fma.
// ---------------------------------------------------------------------------
#define RPB 4
#define JCH 32

__global__ void __launch_bounds__(256) attn_kernel(
    const float* __restrict__ mask, float* __restrict__ out)
{
    const int gg = blockIdx.y;
    const int r0 = blockIdx.x * RPB;
    const int h  = threadIdx.x;

    __shared__ float ysh[JCH * H];       // 32 KB
    __shared__ int acts[NV];
    __shared__ int s_cnt[2];
    __shared__ int s_nact;

    // ---- in-block compaction (threads 0..63) ----
    bool act = false;
    unsigned bal = 0;
    if (h < NV) {
        act = (mask[gg * NV + h] > 0.5f);
        bal = __ballot_sync(0xffffffffu, act);
        if ((h & 31) == 0) s_cnt[h >> 5] = __popc(bal);
    }
    __syncthreads();
    if (h < NV) {
        const int warp = h >> 5, lane = h & 31;
        const int a0 = s_cnt[0], a1 = s_cnt[1];
        const int nact = a0 + a1;
        const int pre  = __popc(bal & ((1u << lane) - 1u));
        const int preI = lane - pre;
        const int pos = act ? ((warp ? a0 : 0) + pre)
                            : (nact + (warp ? (32 - a0) : 0) + preI);
        acts[pos] = h;
        if (h == 0) s_nact = nact;
    }
    __syncthreads();

    const int nact = s_nact;

    float a2[RPB], acc[RPB];
#pragma unroll
    for (int r = 0; r < RPB; r++) {
        const int row = acts[r0 + r];
        a2[r] = 0.5f * g_C[(size_t)(gg * NV + row) * H + h];
        acc[r] = 0.0f;
    }

    const uint32_t ysh_base = (uint32_t)__cvta_generic_to_shared(&ysh[0]);
    const float* yg = g_Y + (size_t)gg * NV * H;

    if (r0 < nact) {
        for (int jb = 0; jb < nact; jb += JCH) {
            const int jn = min(JCH, nact - jb);
            __syncthreads();
            // cp.async fill: jn*64 float4 slots, 256 threads
            {
                const int nslots = jn * (H / 4);
                for (int s = h; s < nslots; s += 256) {
                    const int jrow = s >> 6;          // H/4 = 64 slots per row
                    const int c4   = s & 63;
                    cpa16(ysh_base + (uint32_t)(jrow * H + c4 * 4) * 4,
                          yg + (size_t)acts[jb + jrow] * H + c4 * 4);
                }
                asm volatile("cp.async.commit_group;");
                asm volatile("cp.async.wait_group 0;");
            }
            __syncthreads();

            int jj = 0;
            for (; jj + 4 <= jn; jj += 4) {
                float yv[4];
#pragma unroll
                for (int u = 0; u < 4; u++) yv[u] = ysh[(jj + u) * H + h];
#pragma unroll
                for (int u = 0; u < 4; u++) {
#pragma unroll
                    for (int r = 0; r < RPB; r++) {
                        float x = fmaf(0.5f, yv[u], a2[r]);
                        float th;
                        asm("tanh.approx.f32 %0, %1;" : "=f"(th) : "f"(x));
                        acc[r] += th;
                    }
                }
            }
            for (; jj < jn; jj++) {
                const float yv = ysh[jj * H + h];
#pragma unroll
                for (int r = 0; r < RPB; r++) {
                    float x = fmaf(0.5f, yv, a2[r]);
                    float th;
                    asm("tanh.approx.f32 %0, %1;" : "=f"(th) : "f"(x));
                    acc[r] += th;
                }
            }
        }
    }

    const float inv    = nact ? (1.0f / (float)nact) : 0.0f;
    const float half_n = 0.5f * (float)nact;
#pragma unroll
    for (int r = 0; r < RPB; r++) {
        const int rr = r0 + r;
        const int row = acts[rr];
        float v = (rr < nact) ? (0.5f * acc[r] + half_n) * inv : 0.0f;
        out[(size_t)(gg * NV + row) * H + h] = v;
    }
}

// ---------------------------------------------------------------------------
// kernel_launch
// ---------------------------------------------------------------------------
extern "C" void kernel_launch(void* const* d_in, const int* in_sizes, int n_in,
                              void* d_out, int out_size)
{
    const float *z = nullptr, *mask = nullptr;
    const float *Wc = nullptr, *bc = nullptr, *Wy = nullptr, *by = nullptr;

    for (int i = 0; i < n_in; i++) {
        int s = in_sizes[i];
        const float* p = (const float*)d_in[i];
        if (s == M_ROWS * H)       z = p;
        else if (s == M_ROWS)      mask = p;
        else if (s == H * H)       { if (!Wc) Wc = p; else Wy = p; }
        else if (s == H)           { if (!bc) bc = p; else by = p; }
    }

    float* out = (float*)d_out;

    gemm_tc_kernel<<<dim3(H / 64, M_ROWS / 64, 2), 256>>>(z, Wc, bc, Wy, by);
    attn_kernel<<<dim3(NV / RPB, G), 256>>>(mask, out);
}